// round 10
// baseline (speedup 1.0000x reference)
#include <cuda_runtime.h>
#include <math.h>

#define N_NODES 100000
#define N_EDGES 1600000
#define D_IN    384
#define D_HID   768
#define D_OUT   256

// ---------------- scratch (device globals: no allocation allowed) ----------
__device__ __align__(16) float g_h1 [(size_t)N_NODES * D_HID];  // 307 MB
__device__ __align__(16) float g_h  [(size_t)N_NODES * D_OUT];  // 102 MB
__device__ __align__(16) float g_sum[(size_t)N_NODES * D_OUT];  // 102 MB
__device__ __align__(16) float g_cnt[N_NODES];
__device__ int g_is64;

// ---------------- K0: zero accumulators + detect edge_index dtype ----------
__global__ void k_zero(const void* __restrict__ ei_raw)
{
    size_t i      = (size_t)blockIdx.x * blockDim.x + threadIdx.x;
    size_t stride = (size_t)gridDim.x * blockDim.x;
    size_t n4     = (size_t)N_NODES * D_OUT / 4;
    float4 z = make_float4(0.f, 0.f, 0.f, 0.f);
    for (size_t j = i; j < n4; j += stride)
        reinterpret_cast<float4*>(g_sum)[j] = z;
    for (size_t j = i; j < N_NODES; j += stride)
        g_cnt[j] = 0.f;

    if (blockIdx.x == 0 && threadIdx.x == 0) {
        // If edges are int64 (values < 1e5, nonnegative), every odd 32-bit
        // word is 0. If int32, those words are random indices; P(all 64
        // sampled are zero) ~ 1e-320.
        const unsigned int* w = (const unsigned int*)ei_raw;
        int is64 = 1;
        for (int k = 0; k < 64; k++)
            if (w[2 * k + 1] != 0u) is64 = 0;
        g_is64 = is64;
    }
}

// ---------------- K1: h1 = GELU(LN(x @ W1 + b1)) ----------------------------
// Block = 16 rows x 768 cols. 192 threads, each owns 4 contiguous cols x 16 rows.
__global__ __launch_bounds__(192)
void k_enc1(const float* __restrict__ x,  const float* __restrict__ W1,
            const float* __restrict__ b1, const float* __restrict__ g1,
            const float* __restrict__ be1)
{
    constexpr int ROWS = 16, KT = 32, TC = 4, BD = 192, NW = BD / 32;
    __shared__ float xs[KT][ROWS + 1];
    __shared__ float wsum[ROWS][NW], wsq[ROWS][NW];

    const int row0 = blockIdx.x * ROWS;
    const int tid  = threadIdx.x;
    const int c0   = tid * TC;

    float acc[ROWS][TC];
#pragma unroll
    for (int r = 0; r < ROWS; r++)
#pragma unroll
        for (int j = 0; j < TC; j++) acc[r][j] = 0.f;

    for (int k0 = 0; k0 < D_IN; k0 += KT) {
        for (int i = tid; i < ROWS * KT; i += BD) {
            int r = i >> 5, k = i & 31;
            xs[k][r] = x[(size_t)(row0 + r) * D_IN + k0 + k];
        }
        __syncthreads();
#pragma unroll 8
        for (int k = 0; k < KT; k++) {
            float4 w = *reinterpret_cast<const float4*>(W1 + (size_t)(k0 + k) * D_HID + c0);
#pragma unroll
            for (int r = 0; r < ROWS; r++) {
                float xv = xs[k][r];
                acc[r][0] = fmaf(xv, w.x, acc[r][0]);
                acc[r][1] = fmaf(xv, w.y, acc[r][1]);
                acc[r][2] = fmaf(xv, w.z, acc[r][2]);
                acc[r][3] = fmaf(xv, w.w, acc[r][3]);
            }
        }
        __syncthreads();
    }

    float4 bb = *reinterpret_cast<const float4*>(b1 + c0);
#pragma unroll
    for (int r = 0; r < ROWS; r++) {
        acc[r][0] += bb.x; acc[r][1] += bb.y; acc[r][2] += bb.z; acc[r][3] += bb.w;
    }

    // LayerNorm reduction over the 768 columns (distributed across 192 threads)
    const int lane = tid & 31, warp = tid >> 5;
#pragma unroll
    for (int r = 0; r < ROWS; r++) {
        float s = acc[r][0] + acc[r][1] + acc[r][2] + acc[r][3];
        float q = acc[r][0] * acc[r][0] + acc[r][1] * acc[r][1]
                + acc[r][2] * acc[r][2] + acc[r][3] * acc[r][3];
#pragma unroll
        for (int o = 16; o > 0; o >>= 1) {
            s += __shfl_down_sync(0xffffffffu, s, o);
            q += __shfl_down_sync(0xffffffffu, q, o);
        }
        if (lane == 0) { wsum[r][warp] = s; wsq[r][warp] = q; }
    }
    __syncthreads();

    float mu[ROWS], rs[ROWS];
#pragma unroll
    for (int r = 0; r < ROWS; r++) {
        float s = 0.f, q = 0.f;
#pragma unroll
        for (int w = 0; w < NW; w++) { s += wsum[r][w]; q += wsq[r][w]; }
        float m = s * (1.f / D_HID);
        float v = q * (1.f / D_HID) - m * m;
        mu[r] = m;
        rs[r] = rsqrtf(v + 1e-5f);
    }

    float4 gg = *reinterpret_cast<const float4*>(g1  + c0);
    float4 bt = *reinterpret_cast<const float4*>(be1 + c0);
#pragma unroll
    for (int r = 0; r < ROWS; r++) {
        float4 o;
        float t;
        t = (acc[r][0] - mu[r]) * rs[r] * gg.x + bt.x; o.x = 0.5f * t * (1.f + erff(t * 0.70710678118654752f));
        t = (acc[r][1] - mu[r]) * rs[r] * gg.y + bt.y; o.y = 0.5f * t * (1.f + erff(t * 0.70710678118654752f));
        t = (acc[r][2] - mu[r]) * rs[r] * gg.z + bt.z; o.z = 0.5f * t * (1.f + erff(t * 0.70710678118654752f));
        t = (acc[r][3] - mu[r]) * rs[r] * gg.w + bt.w; o.w = 0.5f * t * (1.f + erff(t * 0.70710678118654752f));
        *reinterpret_cast<float4*>(g_h1 + (size_t)(row0 + r) * D_HID + c0) = o;
    }
}

// ---------------- K2: h = h1 @ W2 + b2 --------------------------------------
// Block = 16 rows x 256 cols. 64 threads, each owns 4 cols x 16 rows.
__global__ __launch_bounds__(64)
void k_enc2(const float* __restrict__ W2, const float* __restrict__ b2)
{
    constexpr int ROWS = 16, KT = 32, TC = 4, BD = 64;
    __shared__ float xs[KT][ROWS + 1];
    const int row0 = blockIdx.x * ROWS;
    const int tid  = threadIdx.x;
    const int c0   = tid * TC;

    float acc[ROWS][TC];
#pragma unroll
    for (int r = 0; r < ROWS; r++)
#pragma unroll
        for (int j = 0; j < TC; j++) acc[r][j] = 0.f;

    for (int k0 = 0; k0 < D_HID; k0 += KT) {
        for (int i = tid; i < ROWS * KT; i += BD) {
            int r = i >> 5, k = i & 31;
            xs[k][r] = g_h1[(size_t)(row0 + r) * D_HID + k0 + k];
        }
        __syncthreads();
#pragma unroll 8
        for (int k = 0; k < KT; k++) {
            float4 w = *reinterpret_cast<const float4*>(W2 + (size_t)(k0 + k) * D_OUT + c0);
#pragma unroll
            for (int r = 0; r < ROWS; r++) {
                float xv = xs[k][r];
                acc[r][0] = fmaf(xv, w.x, acc[r][0]);
                acc[r][1] = fmaf(xv, w.y, acc[r][1]);
                acc[r][2] = fmaf(xv, w.z, acc[r][2]);
                acc[r][3] = fmaf(xv, w.w, acc[r][3]);
            }
        }
        __syncthreads();
    }

    float4 bb = *reinterpret_cast<const float4*>(b2 + c0);
#pragma unroll
    for (int r = 0; r < ROWS; r++) {
        float4 o = make_float4(acc[r][0] + bb.x, acc[r][1] + bb.y,
                               acc[r][2] + bb.z, acc[r][3] + bb.w);
        *reinterpret_cast<float4*>(g_h + (size_t)(row0 + r) * D_OUT + c0) = o;
    }
}

// ---------------- K3: edge scatter (segment-sum + counts) -------------------
// One warp per edge: gather h[src] (2 x float4 per lane), atomic-add into sum[dst].
__global__ void k_scatter(const void* __restrict__ ei_raw)
{
    int gw   = (int)(((size_t)blockIdx.x * blockDim.x + threadIdx.x) >> 5);
    int lane = threadIdx.x & 31;
    if (gw >= N_EDGES) return;

    int s, d;
    if (g_is64) {
        const long long* e = (const long long*)ei_raw;
        s = (int)e[gw];
        d = (int)e[(size_t)N_EDGES + gw];
    } else {
        const int* e = (const int*)ei_raw;
        s = e[gw];
        d = e[N_EDGES + gw];
    }

    const float4* hp = reinterpret_cast<const float4*>(g_h + (size_t)s * D_OUT);
    float*        sp = g_sum + (size_t)d * D_OUT;

    float4 v0 = hp[lane];
    float4 v1 = hp[lane + 32];
    int b0 = lane * 4;
    atomicAdd(sp + b0 + 0, v0.x);
    atomicAdd(sp + b0 + 1, v0.y);
    atomicAdd(sp + b0 + 2, v0.z);
    atomicAdd(sp + b0 + 3, v0.w);
    atomicAdd(sp + 128 + b0 + 0, v1.x);
    atomicAdd(sp + 128 + b0 + 1, v1.y);
    atomicAdd(sp + 128 + b0 + 2, v1.z);
    atomicAdd(sp + 128 + b0 + 3, v1.w);
    if (lane == 0) atomicAdd(&g_cnt[d], 1.0f);
}

// ---------------- K4: out = LN(h + mean@Wl + bl + h@Wr) ---------------------
// Block = 16 rows x 256 cols, full K tiles (mean & h rows) kept in smem.
__global__ __launch_bounds__(64)
void k_sage(const float* __restrict__ Wl, const float* __restrict__ bl,
            const float* __restrict__ Wr, const float* __restrict__ g2,
            const float* __restrict__ be2, float* __restrict__ out)
{
    constexpr int ROWS = 16, TC = 4, BD = 64;
    __shared__ float hs[ROWS][D_OUT];
    __shared__ float ms[ROWS][D_OUT];
    __shared__ float invc[ROWS];
    __shared__ float wsum[ROWS][2], wsq[ROWS][2];

    const int row0 = blockIdx.x * ROWS;
    const int tid  = threadIdx.x;
    const int c0   = tid * TC;

    if (tid < ROWS) invc[tid] = 1.f / fmaxf(g_cnt[row0 + tid], 1.f);
    __syncthreads();

    for (int i = tid; i < ROWS * D_OUT; i += BD) {
        int r = i >> 8, k = i & 255;
        size_t gi = (size_t)(row0 + r) * D_OUT + k;
        hs[r][k] = g_h[gi];
        ms[r][k] = g_sum[gi] * invc[r];
    }
    __syncthreads();

    float acc[ROWS][TC];
#pragma unroll
    for (int r = 0; r < ROWS; r++)
#pragma unroll
        for (int j = 0; j < TC; j++) acc[r][j] = 0.f;

#pragma unroll 2
    for (int k = 0; k < D_OUT; k++) {
        float4 wl = *reinterpret_cast<const float4*>(Wl + (size_t)k * D_OUT + c0);
        float4 wr = *reinterpret_cast<const float4*>(Wr + (size_t)k * D_OUT + c0);
#pragma unroll
        for (int r = 0; r < ROWS; r++) {
            float mv = ms[r][k], hv = hs[r][k];
            acc[r][0] = fmaf(mv, wl.x, fmaf(hv, wr.x, acc[r][0]));
            acc[r][1] = fmaf(mv, wl.y, fmaf(hv, wr.y, acc[r][1]));
            acc[r][2] = fmaf(mv, wl.z, fmaf(hv, wr.z, acc[r][2]));
            acc[r][3] = fmaf(mv, wl.w, fmaf(hv, wr.w, acc[r][3]));
        }
    }

    float4 bb = *reinterpret_cast<const float4*>(bl + c0);
#pragma unroll
    for (int r = 0; r < ROWS; r++) {
        acc[r][0] += bb.x + hs[r][c0 + 0];   // residual: h + sage
        acc[r][1] += bb.y + hs[r][c0 + 1];
        acc[r][2] += bb.z + hs[r][c0 + 2];
        acc[r][3] += bb.w + hs[r][c0 + 3];
    }

    // LayerNorm over 256 columns (64 threads = 2 warps)
    const int lane = tid & 31, warp = tid >> 5;
#pragma unroll
    for (int r = 0; r < ROWS; r++) {
        float s = acc[r][0] + acc[r][1] + acc[r][2] + acc[r][3];
        float q = acc[r][0] * acc[r][0] + acc[r][1] * acc[r][1]
                + acc[r][2] * acc[r][2] + acc[r][3] * acc[r][3];
#pragma unroll
        for (int o = 16; o > 0; o >>= 1) {
            s += __shfl_down_sync(0xffffffffu, s, o);
            q += __shfl_down_sync(0xffffffffu, q, o);
        }
        if (lane == 0) { wsum[r][warp] = s; wsq[r][warp] = q; }
    }
    __syncthreads();

    float mu[ROWS], rs[ROWS];
#pragma unroll
    for (int r = 0; r < ROWS; r++) {
        float s = wsum[r][0] + wsum[r][1];
        float q = wsq[r][0] + wsq[r][1];
        float m = s * (1.f / D_OUT);
        float v = q * (1.f / D_OUT) - m * m;
        mu[r] = m;
        rs[r] = rsqrtf(v + 1e-5f);
    }

    float4 gg = *reinterpret_cast<const float4*>(g2  + c0);
    float4 bt = *reinterpret_cast<const float4*>(be2 + c0);
#pragma unroll
    for (int r = 0; r < ROWS; r++) {
        float4 o;
        o.x = (acc[r][0] - mu[r]) * rs[r] * gg.x + bt.x;
        o.y = (acc[r][1] - mu[r]) * rs[r] * gg.y + bt.y;
        o.z = (acc[r][2] - mu[r]) * rs[r] * gg.z + bt.z;
        o.w = (acc[r][3] - mu[r]) * rs[r] * gg.w + bt.w;
        *reinterpret_cast<float4*>(out + (size_t)(row0 + r) * D_OUT + c0) = o;
    }
}

// ---------------- launch -----------------------------------------------------
extern "C" void kernel_launch(void* const* d_in, const int* in_sizes, int n_in,
                              void* d_out, int out_size)
{
    const float* x   = (const float*)d_in[0];
    const void*  ei  = d_in[1];                  // int64 or int32, detected on device
    const float* W1  = (const float*)d_in[2];
    const float* b1  = (const float*)d_in[3];
    const float* g1  = (const float*)d_in[4];
    const float* be1 = (const float*)d_in[5];
    const float* W2  = (const float*)d_in[6];
    const float* b2  = (const float*)d_in[7];
    const float* Wl  = (const float*)d_in[8];
    const float* bl  = (const float*)d_in[9];
    const float* Wr  = (const float*)d_in[10];
    const float* g2  = (const float*)d_in[11];
    const float* be2 = (const float*)d_in[12];
    float* out = (float*)d_out;

    (void)in_sizes; (void)n_in; (void)out_size;

    k_zero   <<<2048, 256>>>(ei);
    k_enc1   <<<N_NODES / 16, 192>>>(x, W1, b1, g1, be1);
    k_enc2   <<<N_NODES / 16, 64>>>(W2, b2);
    k_scatter<<<(N_EDGES * 32) / 256, 256>>>(ei);
    k_sage   <<<N_NODES / 16, 64>>>(Wl, bl, Wr, g2, be2, out);
}

// round 11
// speedup vs baseline: 1.0028x; 1.0028x over previous
#include <cuda_runtime.h>
#include <math.h>

#define N_NODES 100000
#define N_EDGES 1600000
#define D_IN    384
#define D_HID   768
#define D_OUT   256

// ---------------- scratch (device globals: no allocation allowed) ----------
__device__ __align__(16) float g_h1 [(size_t)N_NODES * D_HID];  // 307 MB
__device__ __align__(16) float g_h  [(size_t)N_NODES * D_OUT];  // 102 MB
__device__ __align__(16) float g_sum[(size_t)N_NODES * D_OUT];  // 102 MB
__device__ __align__(16) float g_cnt[N_NODES];
__device__ int g_is64;

// ---------------- K0: zero accumulators + detect edge_index dtype ----------
__global__ void k_zero(const void* __restrict__ ei_raw)
{
    size_t i      = (size_t)blockIdx.x * blockDim.x + threadIdx.x;
    size_t stride = (size_t)gridDim.x * blockDim.x;
    size_t n4     = (size_t)N_NODES * D_OUT / 4;
    float4 z = make_float4(0.f, 0.f, 0.f, 0.f);
    for (size_t j = i; j < n4; j += stride)
        reinterpret_cast<float4*>(g_sum)[j] = z;
    for (size_t j = i; j < N_NODES; j += stride)
        g_cnt[j] = 0.f;

    if (blockIdx.x == 0 && threadIdx.x == 0) {
        // If edges are int64 (values < 1e5, nonnegative), every odd 32-bit
        // word is 0. If int32, those words are random indices; P(all 64
        // sampled are zero) ~ 1e-320.
        const unsigned int* w = (const unsigned int*)ei_raw;
        int is64 = 1;
        for (int k = 0; k < 64; k++)
            if (w[2 * k + 1] != 0u) is64 = 0;
        g_is64 = is64;
    }
}

// ---------------- K1: h1 = GELU(LN(x @ W1 + b1)) ----------------------------
// Block = 16 rows x 768 cols. 192 threads, each owns 4 contiguous cols x 16 rows.
__global__ __launch_bounds__(192)
void k_enc1(const float* __restrict__ x,  const float* __restrict__ W1,
            const float* __restrict__ b1, const float* __restrict__ g1,
            const float* __restrict__ be1)
{
    constexpr int ROWS = 16, KT = 32, TC = 4, BD = 192, NW = BD / 32;
    __shared__ float xs[KT][ROWS + 1];
    __shared__ float wsum[ROWS][NW], wsq[ROWS][NW];

    const int row0 = blockIdx.x * ROWS;
    const int tid  = threadIdx.x;
    const int c0   = tid * TC;

    float acc[ROWS][TC];
#pragma unroll
    for (int r = 0; r < ROWS; r++)
#pragma unroll
        for (int j = 0; j < TC; j++) acc[r][j] = 0.f;

    for (int k0 = 0; k0 < D_IN; k0 += KT) {
        for (int i = tid; i < ROWS * KT; i += BD) {
            int r = i >> 5, k = i & 31;
            xs[k][r] = x[(size_t)(row0 + r) * D_IN + k0 + k];
        }
        __syncthreads();
#pragma unroll 8
        for (int k = 0; k < KT; k++) {
            float4 w = *reinterpret_cast<const float4*>(W1 + (size_t)(k0 + k) * D_HID + c0);
#pragma unroll
            for (int r = 0; r < ROWS; r++) {
                float xv = xs[k][r];
                acc[r][0] = fmaf(xv, w.x, acc[r][0]);
                acc[r][1] = fmaf(xv, w.y, acc[r][1]);
                acc[r][2] = fmaf(xv, w.z, acc[r][2]);
                acc[r][3] = fmaf(xv, w.w, acc[r][3]);
            }
        }
        __syncthreads();
    }

    float4 bb = *reinterpret_cast<const float4*>(b1 + c0);
#pragma unroll
    for (int r = 0; r < ROWS; r++) {
        acc[r][0] += bb.x; acc[r][1] += bb.y; acc[r][2] += bb.z; acc[r][3] += bb.w;
    }

    // LayerNorm reduction over the 768 columns (distributed across 192 threads)
    const int lane = tid & 31, warp = tid >> 5;
#pragma unroll
    for (int r = 0; r < ROWS; r++) {
        float s = acc[r][0] + acc[r][1] + acc[r][2] + acc[r][3];
        float q = acc[r][0] * acc[r][0] + acc[r][1] * acc[r][1]
                + acc[r][2] * acc[r][2] + acc[r][3] * acc[r][3];
#pragma unroll
        for (int o = 16; o > 0; o >>= 1) {
            s += __shfl_down_sync(0xffffffffu, s, o);
            q += __shfl_down_sync(0xffffffffu, q, o);
        }
        if (lane == 0) { wsum[r][warp] = s; wsq[r][warp] = q; }
    }
    __syncthreads();

    float mu[ROWS], rs[ROWS];
#pragma unroll
    for (int r = 0; r < ROWS; r++) {
        float s = 0.f, q = 0.f;
#pragma unroll
        for (int w = 0; w < NW; w++) { s += wsum[r][w]; q += wsq[r][w]; }
        float m = s * (1.f / D_HID);
        float v = q * (1.f / D_HID) - m * m;
        mu[r] = m;
        rs[r] = rsqrtf(v + 1e-5f);
    }

    float4 gg = *reinterpret_cast<const float4*>(g1  + c0);
    float4 bt = *reinterpret_cast<const float4*>(be1 + c0);
#pragma unroll
    for (int r = 0; r < ROWS; r++) {
        float4 o;
        float t;
        t = (acc[r][0] - mu[r]) * rs[r] * gg.x + bt.x; o.x = 0.5f * t * (1.f + erff(t * 0.70710678118654752f));
        t = (acc[r][1] - mu[r]) * rs[r] * gg.y + bt.y; o.y = 0.5f * t * (1.f + erff(t * 0.70710678118654752f));
        t = (acc[r][2] - mu[r]) * rs[r] * gg.z + bt.z; o.z = 0.5f * t * (1.f + erff(t * 0.70710678118654752f));
        t = (acc[r][3] - mu[r]) * rs[r] * gg.w + bt.w; o.w = 0.5f * t * (1.f + erff(t * 0.70710678118654752f));
        *reinterpret_cast<float4*>(g_h1 + (size_t)(row0 + r) * D_HID + c0) = o;
    }
}

// ---------------- K2: h = h1 @ W2 + b2 --------------------------------------
// Block = 16 rows x 256 cols. 64 threads, each owns 4 cols x 16 rows.
__global__ __launch_bounds__(64)
void k_enc2(const float* __restrict__ W2, const float* __restrict__ b2)
{
    constexpr int ROWS = 16, KT = 32, TC = 4, BD = 64;
    __shared__ float xs[KT][ROWS + 1];
    const int row0 = blockIdx.x * ROWS;
    const int tid  = threadIdx.x;
    const int c0   = tid * TC;

    float acc[ROWS][TC];
#pragma unroll
    for (int r = 0; r < ROWS; r++)
#pragma unroll
        for (int j = 0; j < TC; j++) acc[r][j] = 0.f;

    for (int k0 = 0; k0 < D_HID; k0 += KT) {
        for (int i = tid; i < ROWS * KT; i += BD) {
            int r = i >> 5, k = i & 31;
            xs[k][r] = g_h1[(size_t)(row0 + r) * D_HID + k0 + k];
        }
        __syncthreads();
#pragma unroll 8
        for (int k = 0; k < KT; k++) {
            float4 w = *reinterpret_cast<const float4*>(W2 + (size_t)(k0 + k) * D_OUT + c0);
#pragma unroll
            for (int r = 0; r < ROWS; r++) {
                float xv = xs[k][r];
                acc[r][0] = fmaf(xv, w.x, acc[r][0]);
                acc[r][1] = fmaf(xv, w.y, acc[r][1]);
                acc[r][2] = fmaf(xv, w.z, acc[r][2]);
                acc[r][3] = fmaf(xv, w.w, acc[r][3]);
            }
        }
        __syncthreads();
    }

    float4 bb = *reinterpret_cast<const float4*>(b2 + c0);
#pragma unroll
    for (int r = 0; r < ROWS; r++) {
        float4 o = make_float4(acc[r][0] + bb.x, acc[r][1] + bb.y,
                               acc[r][2] + bb.z, acc[r][3] + bb.w);
        *reinterpret_cast<float4*>(g_h + (size_t)(row0 + r) * D_OUT + c0) = o;
    }
}

// ---------------- K3: edge scatter (segment-sum + counts) -------------------
// One warp per edge: gather h[src] (2 x float4 per lane), atomic-add into sum[dst].
__global__ void k_scatter(const void* __restrict__ ei_raw)
{
    int gw   = (int)(((size_t)blockIdx.x * blockDim.x + threadIdx.x) >> 5);
    int lane = threadIdx.x & 31;
    if (gw >= N_EDGES) return;

    int s, d;
    if (g_is64) {
        const long long* e = (const long long*)ei_raw;
        s = (int)e[gw];
        d = (int)e[(size_t)N_EDGES + gw];
    } else {
        const int* e = (const int*)ei_raw;
        s = e[gw];
        d = e[N_EDGES + gw];
    }

    const float4* hp = reinterpret_cast<const float4*>(g_h + (size_t)s * D_OUT);
    float*        sp = g_sum + (size_t)d * D_OUT;

    float4 v0 = hp[lane];
    float4 v1 = hp[lane + 32];
    int b0 = lane * 4;
    atomicAdd(sp + b0 + 0, v0.x);
    atomicAdd(sp + b0 + 1, v0.y);
    atomicAdd(sp + b0 + 2, v0.z);
    atomicAdd(sp + b0 + 3, v0.w);
    atomicAdd(sp + 128 + b0 + 0, v1.x);
    atomicAdd(sp + 128 + b0 + 1, v1.y);
    atomicAdd(sp + 128 + b0 + 2, v1.z);
    atomicAdd(sp + 128 + b0 + 3, v1.w);
    if (lane == 0) atomicAdd(&g_cnt[d], 1.0f);
}

// ---------------- K4: out = LN(h + mean@Wl + bl + h@Wr) ---------------------
// Block = 16 rows x 256 cols, full K tiles (mean & h rows) kept in smem.
__global__ __launch_bounds__(64)
void k_sage(const float* __restrict__ Wl, const float* __restrict__ bl,
            const float* __restrict__ Wr, const float* __restrict__ g2,
            const float* __restrict__ be2, float* __restrict__ out)
{
    constexpr int ROWS = 16, TC = 4, BD = 64;
    __shared__ float hs[ROWS][D_OUT];
    __shared__ float ms[ROWS][D_OUT];
    __shared__ float invc[ROWS];
    __shared__ float wsum[ROWS][2], wsq[ROWS][2];

    const int row0 = blockIdx.x * ROWS;
    const int tid  = threadIdx.x;
    const int c0   = tid * TC;

    if (tid < ROWS) invc[tid] = 1.f / fmaxf(g_cnt[row0 + tid], 1.f);
    __syncthreads();

    for (int i = tid; i < ROWS * D_OUT; i += BD) {
        int r = i >> 8, k = i & 255;
        size_t gi = (size_t)(row0 + r) * D_OUT + k;
        hs[r][k] = g_h[gi];
        ms[r][k] = g_sum[gi] * invc[r];
    }
    __syncthreads();

    float acc[ROWS][TC];
#pragma unroll
    for (int r = 0; r < ROWS; r++)
#pragma unroll
        for (int j = 0; j < TC; j++) acc[r][j] = 0.f;

#pragma unroll 2
    for (int k = 0; k < D_OUT; k++) {
        float4 wl = *reinterpret_cast<const float4*>(Wl + (size_t)k * D_OUT + c0);
        float4 wr = *reinterpret_cast<const float4*>(Wr + (size_t)k * D_OUT + c0);
#pragma unroll
        for (int r = 0; r < ROWS; r++) {
            float mv = ms[r][k], hv = hs[r][k];
            acc[r][0] = fmaf(mv, wl.x, fmaf(hv, wr.x, acc[r][0]));
            acc[r][1] = fmaf(mv, wl.y, fmaf(hv, wr.y, acc[r][1]));
            acc[r][2] = fmaf(mv, wl.z, fmaf(hv, wr.z, acc[r][2]));
            acc[r][3] = fmaf(mv, wl.w, fmaf(hv, wr.w, acc[r][3]));
        }
    }

    float4 bb = *reinterpret_cast<const float4*>(bl + c0);
#pragma unroll
    for (int r = 0; r < ROWS; r++) {
        acc[r][0] += bb.x + hs[r][c0 + 0];   // residual: h + sage
        acc[r][1] += bb.y + hs[r][c0 + 1];
        acc[r][2] += bb.z + hs[r][c0 + 2];
        acc[r][3] += bb.w + hs[r][c0 + 3];
    }

    // LayerNorm over 256 columns (64 threads = 2 warps)
    const int lane = tid & 31, warp = tid >> 5;
#pragma unroll
    for (int r = 0; r < ROWS; r++) {
        float s = acc[r][0] + acc[r][1] + acc[r][2] + acc[r][3];
        float q = acc[r][0] * acc[r][0] + acc[r][1] * acc[r][1]
                + acc[r][2] * acc[r][2] + acc[r][3] * acc[r][3];
#pragma unroll
        for (int o = 16; o > 0; o >>= 1) {
            s += __shfl_down_sync(0xffffffffu, s, o);
            q += __shfl_down_sync(0xffffffffu, q, o);
        }
        if (lane == 0) { wsum[r][warp] = s; wsq[r][warp] = q; }
    }
    __syncthreads();

    float mu[ROWS], rs[ROWS];
#pragma unroll
    for (int r = 0; r < ROWS; r++) {
        float s = wsum[r][0] + wsum[r][1];
        float q = wsq[r][0] + wsq[r][1];
        float m = s * (1.f / D_OUT);
        float v = q * (1.f / D_OUT) - m * m;
        mu[r] = m;
        rs[r] = rsqrtf(v + 1e-5f);
    }

    float4 gg = *reinterpret_cast<const float4*>(g2  + c0);
    float4 bt = *reinterpret_cast<const float4*>(be2 + c0);
#pragma unroll
    for (int r = 0; r < ROWS; r++) {
        float4 o;
        o.x = (acc[r][0] - mu[r]) * rs[r] * gg.x + bt.x;
        o.y = (acc[r][1] - mu[r]) * rs[r] * gg.y + bt.y;
        o.z = (acc[r][2] - mu[r]) * rs[r] * gg.z + bt.z;
        o.w = (acc[r][3] - mu[r]) * rs[r] * gg.w + bt.w;
        *reinterpret_cast<float4*>(out + (size_t)(row0 + r) * D_OUT + c0) = o;
    }
}

// ---------------- launch -----------------------------------------------------
extern "C" void kernel_launch(void* const* d_in, const int* in_sizes, int n_in,
                              void* d_out, int out_size)
{
    const float* x   = (const float*)d_in[0];
    const void*  ei  = d_in[1];                  // int64 or int32, detected on device
    const float* W1  = (const float*)d_in[2];
    const float* b1  = (const float*)d_in[3];
    const float* g1  = (const float*)d_in[4];
    const float* be1 = (const float*)d_in[5];
    const float* W2  = (const float*)d_in[6];
    const float* b2  = (const float*)d_in[7];
    const float* Wl  = (const float*)d_in[8];
    const float* bl  = (const float*)d_in[9];
    const float* Wr  = (const float*)d_in[10];
    const float* g2  = (const float*)d_in[11];
    const float* be2 = (const float*)d_in[12];
    float* out = (float*)d_out;

    (void)in_sizes; (void)n_in; (void)out_size;

    k_zero   <<<2048, 256>>>(ei);
    k_enc1   <<<N_NODES / 16, 192>>>(x, W1, b1, g1, be1);
    k_enc2   <<<N_NODES / 16, 64>>>(W2, b2);
    k_scatter<<<(N_EDGES * 32) / 256, 256>>>(ei);
    k_sage   <<<N_NODES / 16, 64>>>(Wl, bl, Wr, g2, be2, out);
}